// round 15
// baseline (speedup 1.0000x reference)
#include <cuda_runtime.h>
#include <cuda_fp16.h>
#include <cstdint>

#define BATCH 64
#define NW    256
#define HDIM  768
#define BM    128
#define BN    256
#define BK    32
#define NIT   (HDIM / BK)   // 24
#define STAGES 4
#define NTHREADS 256
#define RSTRIDE 36           // words per tile row (32 + 4 pad)

#define K1f    0.1f
#define Bpf    1.2f
#define AVDLf  50.0f
#define ABf    ((float)(0.1 / 768.0))   /* ALPHA*BETA */
#define EMWf   0.9f                     /* 1 - BETA   */

// ---- smem word map ----
#define W_QK    0              // 128 words
#define W_DK    128            // 256
#define W_DTF   384            // 256
#define W_RED   640            // 512 (4 x 128)
#define W_P8    1152           // 8
#define W_R2    1160           // 4
#define W_TILE  1280           // 4 stages x (A 128*36 + B 256*36)
#define A_W     (BM * RSTRIDE)            // 4608
#define STAGE_W (A_W + BN * RSTRIDE)      // 13824
#define SMEM_BYTES ((W_TILE + STAGES * STAGE_W) * 4)   // 226304

__device__ __forceinline__ void mma_f16(float& c0, float& c1, float& c2, float& c3,
                                        unsigned a0, unsigned a1, unsigned a2, unsigned a3,
                                        unsigned b0, unsigned b1) {
    asm volatile(
        "mma.sync.aligned.m16n8k16.row.col.f32.f16.f16.f32 "
        "{%0,%1,%2,%3}, {%4,%5,%6,%7}, {%8,%9}, {%0,%1,%2,%3};"
        : "+f"(c0), "+f"(c1), "+f"(c2), "+f"(c3)
        : "r"(a0), "r"(a1), "r"(a2), "r"(a3), "r"(b0), "r"(b1));
}

__device__ __forceinline__ void cp16(unsigned dst_smem, const void* src) {
    asm volatile("cp.async.cg.shared.global [%0], [%1], 16;" :: "r"(dst_smem), "l"(src));
}
__device__ __forceinline__ void cp_commit() { asm volatile("cp.async.commit_group;"); }

__device__ __forceinline__ unsigned pkh2(float2 v) {
    __half2 h = __floats2half2_rn(v.x, v.y);   // v.x -> low half
    return *(unsigned*)&h;
}

// ============================================================
// GEMM + fully fused epilogue. grid (2, 64). 256 thr, 8 warps,
// warp grid 2(M) x 4(N), warp tile 64x64. fp16 m16n8k16 MMA over
// fp32 smem tiles (float2 -> f16x2 at fragment load). 4-stage
// cp.async ring, prefetch distance 3, one barrier per iter.
// ============================================================
__global__ __launch_bounds__(NTHREADS, 1)
void gemm_kernel(const float* __restrict__ qrep, const float* __restrict__ drep,
                 const float* __restrict__ qtw,
                 const int* __restrict__ qids, const int* __restrict__ dids,
                 const int* __restrict__ dtfs, float* __restrict__ otf,
                 float* __restrict__ score) {
    extern __shared__ unsigned sm[];
    const int b   = blockIdx.y;
    const int bm0 = blockIdx.x * BM;
    const int tid = threadIdx.x;
    const int lane = tid & 31;
    const int warpId = tid >> 5;
    const int wm0 = (warpId >> 2) * 64;
    const int wn0 = (warpId & 3) * 64;
    const int q  = lane & 3;
    const int lq = lane >> 2;

    const float* Ag = qrep + ((size_t)b * NW + bm0) * HDIM;
    const float* Bg = drep + (size_t)b * NW * HDIM;

    const unsigned smbase = (unsigned)__cvta_generic_to_shared(sm);

    // ---- epilogue tables (dedicated region, untouched by tile ring) ----
    if (tid < BM) {
        int4 v = ((const int4*)qids)[b * NW + bm0 + tid];
        sm[W_QK + tid] = (unsigned)v.x | ((unsigned)v.y << 8) | ((unsigned)v.z << 16) | ((unsigned)v.w << 24);
    }
    {
        int4 v = ((const int4*)dids)[b * NW + tid];
        sm[W_DK + tid] = (unsigned)v.x | ((unsigned)v.y << 8) | ((unsigned)v.z << 16) | ((unsigned)v.w << 24);
        ((float*)sm)[W_DTF + tid] = (float)dtfs[b * NW + tid];
    }

    float acc[4][8][4];
#pragma unroll
    for (int i = 0; i < 4; i++)
#pragma unroll
        for (int j = 0; j < 8; j++)
#pragma unroll
            for (int k = 0; k < 4; k++) acc[i][j][k] = 0.0f;

    // ---- async tile loaders (16B chunks, padded rows: 36 words) ----
    auto loadA = [&](int it, int s) {
        const float* src = Ag + it * BK;
        unsigned dstb = smbase + (W_TILE + s * STAGE_W) * 4;
#pragma unroll
        for (int i = 0; i < 4; i++) {
            int c = tid + i * NTHREADS;
            int r = c >> 3, g = c & 7;
            cp16(dstb + (unsigned)(r * RSTRIDE + g * 4) * 4, src + (size_t)r * HDIM + g * 4);
        }
    };
    auto loadB = [&](int it, int s) {
        const float* src = Bg + it * BK;
        unsigned dstb = smbase + (W_TILE + s * STAGE_W + A_W) * 4;
#pragma unroll
        for (int i = 0; i < 8; i++) {
            int c = tid + i * NTHREADS;
            int r = c >> 3, g = c & 7;
            cp16(dstb + (unsigned)(r * RSTRIDE + g * 4) * 4, src + (size_t)r * HDIM + g * 4);
        }
    };

    // prologue: fill stages 0..2
    loadA(0, 0); loadB(0, 0); cp_commit();
    loadA(1, 1); loadB(1, 1); cp_commit();
    loadA(2, 2); loadB(2, 2); cp_commit();

    for (int it = 0; it < NIT; ++it) {
        asm volatile("cp.async.wait_group 2;");
        __syncthreads();   // tile (it) visible; all reads of stage (it-1) done

        const int pf = it + 3;
        if (pf < NIT) { loadA(pf, pf & 3); loadB(pf, pf & 3); }
        cp_commit();       // empty groups at tail keep the count uniform

        const float* Ast = (const float*)(sm + W_TILE + (it & 3) * STAGE_W);
        const float* Bst = Ast + A_W;

#pragma unroll
        for (int kc = 0; kc < 2; kc++) {       // K-step of 16
            const int k0 = kc * 16 + 2 * q;
            unsigned aa[4][4], bb[8][2];
#pragma unroll
            for (int mi = 0; mi < 4; mi++) {
                const float* base = Ast + (wm0 + mi * 16 + lq) * RSTRIDE + k0;
                aa[mi][0] = pkh2(*(const float2*)(base));
                aa[mi][1] = pkh2(*(const float2*)(base + 8 * RSTRIDE));
                aa[mi][2] = pkh2(*(const float2*)(base + 8));
                aa[mi][3] = pkh2(*(const float2*)(base + 8 * RSTRIDE + 8));
            }
#pragma unroll
            for (int ni = 0; ni < 8; ni++) {
                const float* base = Bst + (wn0 + ni * 8 + lq) * RSTRIDE + k0;
                bb[ni][0] = pkh2(*(const float2*)(base));
                bb[ni][1] = pkh2(*(const float2*)(base + 8));
            }
#pragma unroll
            for (int mi = 0; mi < 4; mi++)
#pragma unroll
                for (int ni = 0; ni < 8; ni++)
                    mma_f16(acc[mi][ni][0], acc[mi][ni][1], acc[mi][ni][2], acc[mi][ni][3],
                            aa[mi][0], aa[mi][1], aa[mi][2], aa[mi][3],
                            bb[ni][0], bb[ni][1]);
        }
    }

    // ---------------- epilogue ----------------
    const unsigned* qk_s  = sm + W_QK;
    const unsigned* dk_s  = sm + W_DK;
    const float*    dtf_s = (const float*)sm + W_DTF;
    float*          red_s = (float*)sm + W_RED;

    // dl partials: each warp reduces its own 32 dtf entries
    {
        float p = dtf_s[warpId * 32 + lane];
#pragma unroll
        for (int o = 16; o > 0; o >>= 1) p += __shfl_xor_sync(0xffffffff, p, o);
        if (lane == 0) ((float*)sm)[W_P8 + warpId] = p;
    }

    float* outb = otf + ((size_t)b * NW + bm0) * NW;

#pragma unroll
    for (int mi = 0; mi < 4; mi++) {
        int r0 = wm0 + mi * 16 + lq, r1 = r0 + 8;
        unsigned qk0 = qk_s[r0], qk1 = qk_s[r1];
        float mq0 = qk0 ? 1.0f : 0.0f, mq1 = qk1 ? 1.0f : 0.0f;
        float rs0 = 0.0f, rs1 = 0.0f;
#pragma unroll
        for (int ni = 0; ni < 8; ni++) {
            int c = wn0 + ni * 8 + q * 2;
            unsigned dk0 = dk_s[c], dk1 = dk_s[c + 1];
            float md0 = dk0 ? 1.0f : 0.0f, md1 = dk1 ? 1.0f : 0.0f;
            float tf0 = dtf_s[c], tf1 = dtf_s[c + 1];
            float v00 = acc[mi][ni][0] * (mq0 * md0);
            float v01 = acc[mi][ni][1] * (mq0 * md1);
            float v10 = acc[mi][ni][2] * (mq1 * md0);
            float v11 = acc[mi][ni][3] * (mq1 * md1);
            *(float2*)(outb + (size_t)r0 * NW + c) = make_float2(v00, v01);
            *(float2*)(outb + (size_t)r1 * NW + c) = make_float2(v10, v11);
            rs0 += (v00 * ABf + (qk0 == dk0 ? EMWf : 0.0f)) * tf0
                 + (v01 * ABf + (qk0 == dk1 ? EMWf : 0.0f)) * tf1;
            rs1 += (v10 * ABf + (qk1 == dk0 ? EMWf : 0.0f)) * tf0
                 + (v11 * ABf + (qk1 == dk1 ? EMWf : 0.0f)) * tf1;
        }
        rs0 += __shfl_xor_sync(0xffffffff, rs0, 1);
        rs0 += __shfl_xor_sync(0xffffffff, rs0, 2);
        rs1 += __shfl_xor_sync(0xffffffff, rs1, 1);
        rs1 += __shfl_xor_sync(0xffffffff, rs1, 2);
        if (q == 0) {
            red_s[(warpId & 3) * BM + r0] = rs0;
            red_s[(warpId & 3) * BM + r1] = rs1;
        }
    }
    __syncthreads();

    // ---- fused BM25 finish: per-CTA partial score, one atomicAdd ----
    float val = 0.0f;
    if (tid < BM) {
        const float* p8 = (const float*)sm + W_P8;
        float dl = ((p8[0] + p8[1]) + (p8[2] + p8[3])) + ((p8[4] + p8[5]) + (p8[6] + p8[7]));
        float etdf = (red_s[tid] + red_s[BM + tid]) + (red_s[2 * BM + tid] + red_s[3 * BM + tid]);
        float denom = etdf * (1.0f + K1f);
        float nom   = etdf + K1f * (1.0f - Bpf + Bpf * dl / AVDLf);
        val = qtw[b * NW + bm0 + tid] * (denom / (nom + 1e-8f));
    }
#pragma unroll
    for (int o = 16; o > 0; o >>= 1) val += __shfl_xor_sync(0xffffffff, val, o);
    if (lane == 0 && warpId < 4) ((float*)sm)[W_R2 + warpId] = val;
    __syncthreads();
    if (tid == 0) {
        const float* r2 = (const float*)sm + W_R2;
        // 2 CTAs per batch: float add of two values is commutative -> deterministic
        atomicAdd(score + b, (r2[0] + r2[1]) + (r2[2] + r2[3]));
    }
}

// ============================================================
extern "C" void kernel_launch(void* const* d_in, const int* in_sizes, int n_in,
                              void* d_out, int out_size) {
    const float* q_rep = (const float*)d_in[0];
    const float* d_rep = (const float*)d_in[1];
    const float* qtw   = (const float*)d_in[2];
    const int*   qids  = (const int*)d_in[3];
    const int*   dids  = (const int*)d_in[4];
    const int*   dtfs  = (const int*)d_in[5];

    float* out = (float*)d_out;
    float* otf = out + BATCH;  // d_expanded_tf region

    cudaMemsetAsync(out, 0, BATCH * sizeof(float));
    cudaFuncSetAttribute(gemm_kernel, cudaFuncAttributeMaxDynamicSharedMemorySize, SMEM_BYTES);

    dim3 grid(NW / BM, BATCH);  // (2, 64)
    gemm_kernel<<<grid, NTHREADS, SMEM_BYTES>>>(q_rep, d_rep, qtw, qids, dids, dtfs, otf, out);
}

// round 16
// speedup vs baseline: 1.8901x; 1.8901x over previous
#include <cuda_runtime.h>
#include <cuda_fp16.h>
#include <cstdint>

#define BATCH 64
#define NW    256
#define HDIM  768
#define BM    128
#define BN    256
#define BK    32
#define NIT   (HDIM / BK)   // 24
#define NTHREADS 256

#define K1f    0.1f
#define Bpf    1.2f
#define AVDLf  50.0f
#define ABf    ((float)(0.1 / 768.0))   /* ALPHA*BETA */
#define EMWf   0.9f                     /* 1 - BETA   */

// ---- smem word map ----
#define W_QK    0              // 128 words
#define W_DK    128            // 256
#define W_DTF   384            // 256
#define W_RED   640            // 512 (4 x 128)
#define W_P8    1152           // 8
#define W_R2    1160           // 4
#define W_F16   1280           // fp16 tiles: 2 bufs x (A 8192B + B 16384B)
#define F16_BUF_BYTES 24576
#define W_STG   13568          // fp32 ring: 3 stages x 12288 words
#define STAGE_W 12288
#define SMEM_BYTES ((W_STG + 3 * STAGE_W) * 4)   // 201728

__device__ __forceinline__ void mma_f16(float& c0, float& c1, float& c2, float& c3,
                                        unsigned a0, unsigned a1, unsigned a2, unsigned a3,
                                        unsigned b0, unsigned b1) {
    asm volatile(
        "mma.sync.aligned.m16n8k16.row.col.f32.f16.f16.f32 "
        "{%0,%1,%2,%3}, {%4,%5,%6,%7}, {%8,%9}, {%0,%1,%2,%3};"
        : "+f"(c0), "+f"(c1), "+f"(c2), "+f"(c3)
        : "r"(a0), "r"(a1), "r"(a2), "r"(a3), "r"(b0), "r"(b1));
}

#define LDSM_X4(r0, r1, r2, r3, addr) \
    asm volatile("ldmatrix.sync.aligned.m8n8.x4.shared.b16 {%0,%1,%2,%3}, [%4];" \
        : "=r"(r0), "=r"(r1), "=r"(r2), "=r"(r3) : "r"(addr))

__device__ __forceinline__ void cp16(unsigned dst_smem, const void* src) {
    asm volatile("cp.async.cg.shared.global [%0], [%1], 16;" :: "r"(dst_smem), "l"(src));
}
__device__ __forceinline__ void cp_commit() { asm volatile("cp.async.commit_group;"); }

__device__ __forceinline__ unsigned pk(float lo, float hi) {
    __half2 h = __floats2half2_rn(lo, hi);   // lo -> low 16 bits
    return *(unsigned*)&h;
}

// ============================================================
// GEMM + fully fused epilogue. grid (2, 64). 256 thr, 8 warps,
// warp grid 2(M) x 4(N), warp tile 64x64. fp16 m16n8k16 MMA.
// Pipeline: cp.async fp32 ring (3 stages) -> in-smem conversion
// pass -> fp16 ldmatrix tiles (2 bufs) -> ldmatrix.x4 + MMA.
// ============================================================
__global__ __launch_bounds__(NTHREADS, 1)
void gemm_kernel(const float* __restrict__ qrep, const float* __restrict__ drep,
                 const float* __restrict__ qtw,
                 const int* __restrict__ qids, const int* __restrict__ dids,
                 const int* __restrict__ dtfs, float* __restrict__ otf,
                 float* __restrict__ score) {
    extern __shared__ unsigned sm[];
    const int b   = blockIdx.y;
    const int bm0 = blockIdx.x * BM;
    const int tid = threadIdx.x;
    const int lane = tid & 31;
    const int warpId = tid >> 5;
    const int wm0 = (warpId >> 2) * 64;
    const int wn0 = (warpId & 3) * 64;
    const int q  = lane & 3;
    const int lq = lane >> 2;

    const float* Ag = qrep + ((size_t)b * NW + bm0) * HDIM;
    const float* Bg = drep + (size_t)b * NW * HDIM;

    const unsigned smbase = (unsigned)__cvta_generic_to_shared(sm);

    // ---- epilogue tables ----
    if (tid < BM) {
        int4 v = ((const int4*)qids)[b * NW + bm0 + tid];
        sm[W_QK + tid] = (unsigned)v.x | ((unsigned)v.y << 8) | ((unsigned)v.z << 16) | ((unsigned)v.w << 24);
    }
    {
        int4 v = ((const int4*)dids)[b * NW + tid];
        sm[W_DK + tid] = (unsigned)v.x | ((unsigned)v.y << 8) | ((unsigned)v.z << 16) | ((unsigned)v.w << 24);
        ((float*)sm)[W_DTF + tid] = (float)dtfs[b * NW + tid];
    }

    float acc[4][8][4];
#pragma unroll
    for (int i = 0; i < 4; i++)
#pragma unroll
        for (int j = 0; j < 8; j++)
#pragma unroll
            for (int k = 0; k < 4; k++) acc[i][j][k] = 0.0f;

    // ---- ldmatrix per-lane geometry (verified in R13) ----
    const int wr    = lane & 7;
    const int a_sel = lane >> 3;
    const int a_g   = a_sel >> 1;
    const int b_g   = (lane >> 3) & 1;
    int a_row[4], b_row[4];
#pragma unroll
    for (int mi = 0; mi < 4; mi++) a_row[mi] = wm0 + mi * 16 + (a_sel & 1) * 8 + wr;
#pragma unroll
    for (int p = 0; p < 4; p++) b_row[p] = wn0 + p * 16 + ((lane >> 4) & 1) * 8 + wr;

    // ---- cp.async fp32 loaders (R11-proven, XOR-swizzled 128B rows) ----
    auto loadA = [&](int it, int s) {
        const float* src = Ag + it * BK;
        unsigned dstb = smbase + (W_STG + s * STAGE_W) * 4;
#pragma unroll
        for (int i = 0; i < 4; i++) {
            int c = tid + i * NTHREADS;
            int r = c >> 3, g = c & 7;
            unsigned w = r * 32 + ((g ^ (r & 7)) << 2);
            cp16(dstb + w * 4, src + (size_t)r * HDIM + g * 4);
        }
    };
    auto loadB = [&](int it, int s) {
        const float* src = Bg + it * BK;
        unsigned dstb = smbase + (W_STG + s * STAGE_W + 4096) * 4;
#pragma unroll
        for (int i = 0; i < 8; i++) {
            int c = tid + i * NTHREADS;
            int r = c >> 3, g = c & 7;
            unsigned w = r * 32 + ((g ^ (r & 7)) << 2);
            cp16(dstb + w * 4, src + (size_t)r * HDIM + g * 4);
        }
    };

    // ---- conversion pass: fp32 stage -> fp16 ldmatrix tiles ----
    auto convert = [&](int s3, int sf) {
        const unsigned* Asrc = sm + W_STG + s3 * STAGE_W;
        const unsigned* Bsrc = Asrc + 4096;
        char* Adst = (char*)sm + W_F16 * 4 + sf * F16_BUF_BYTES;
        char* Bdst = Adst + 8192;
#pragma unroll
        for (int i = 0; i < 2; i++) {          // A: 512 tasks (r, g2)
            int task = tid + i * NTHREADS;
            int r = task >> 2, g2 = task & 3;
            int g0 = 2 * g2, g1 = 2 * g2 + 1;
            float4 v0 = *(const float4*)(Asrc + r * 32 + ((g0 ^ (r & 7)) << 2));
            float4 v1 = *(const float4*)(Asrc + r * 32 + ((g1 ^ (r & 7)) << 2));
            uint4 h = make_uint4(pk(v0.x, v0.y), pk(v0.z, v0.w),
                                 pk(v1.x, v1.y), pk(v1.z, v1.w));
            *(uint4*)(Adst + r * 64 + ((g2 ^ ((r >> 1) & 3)) << 4)) = h;
        }
#pragma unroll
        for (int i = 0; i < 4; i++) {          // B: 1024 tasks
            int task = tid + i * NTHREADS;
            int r = task >> 2, g2 = task & 3;
            int g0 = 2 * g2, g1 = 2 * g2 + 1;
            float4 v0 = *(const float4*)(Bsrc + r * 32 + ((g0 ^ (r & 7)) << 2));
            float4 v1 = *(const float4*)(Bsrc + r * 32 + ((g1 ^ (r & 7)) << 2));
            uint4 h = make_uint4(pk(v0.x, v0.y), pk(v0.z, v0.w),
                                 pk(v1.x, v1.y), pk(v1.z, v1.w));
            *(uint4*)(Bdst + r * 64 + ((g2 ^ ((r >> 1) & 3)) << 4)) = h;
        }
    };

    // prologue: fill stages 0, 1
    loadA(0, 0); loadB(0, 0); cp_commit();
    loadA(1, 1); loadB(1, 1); cp_commit();

    for (int it = 0; it < NIT; ++it) {
        asm volatile("cp.async.wait_group 1;");   // stage(it) arrived
        __syncthreads();                          // + reads of stage(it-1) done

        const int pf = it + 2;
        if (pf < NIT) { loadA(pf, pf % 3); loadB(pf, pf % 3); }
        cp_commit();                              // uniform group count

        convert(it % 3, it & 1);
        __syncthreads();                          // fp16 buf(it&1) ready

        const unsigned Abase = smbase + W_F16 * 4 + (it & 1) * F16_BUF_BYTES;
        const unsigned Bbase = Abase + 8192;

#pragma unroll
        for (int kc = 0; kc < 2; kc++) {          // K-step of 16
            const int gA = 2 * kc + a_g;
            const int gB = 2 * kc + b_g;
            unsigned aa[4][4], bb[4][4];
#pragma unroll
            for (int mi = 0; mi < 4; mi++) {
                unsigned addr = Abase + (unsigned)(a_row[mi] * 64 + ((gA ^ ((a_row[mi] >> 1) & 3)) << 4));
                LDSM_X4(aa[mi][0], aa[mi][1], aa[mi][2], aa[mi][3], addr);
            }
#pragma unroll
            for (int p = 0; p < 4; p++) {
                unsigned addr = Bbase + (unsigned)(b_row[p] * 64 + ((gB ^ ((b_row[p] >> 1) & 3)) << 4));
                LDSM_X4(bb[p][0], bb[p][1], bb[p][2], bb[p][3], addr);
            }
#pragma unroll
            for (int mi = 0; mi < 4; mi++) {
#pragma unroll
                for (int ni = 0; ni < 8; ni++) {
                    const int p = ni >> 1;
                    const unsigned b0 = (ni & 1) ? bb[p][2] : bb[p][0];
                    const unsigned b1 = (ni & 1) ? bb[p][3] : bb[p][1];
                    mma_f16(acc[mi][ni][0], acc[mi][ni][1], acc[mi][ni][2], acc[mi][ni][3],
                            aa[mi][0], aa[mi][1], aa[mi][2], aa[mi][3], b0, b1);
                }
            }
        }
    }

    // ---------------- epilogue ----------------
    const unsigned* qk_s  = sm + W_QK;
    const unsigned* dk_s  = sm + W_DK;
    const float*    dtf_s = (const float*)sm + W_DTF;
    float*          red_s = (float*)sm + W_RED;

    {
        float p = dtf_s[warpId * 32 + lane];
#pragma unroll
        for (int o = 16; o > 0; o >>= 1) p += __shfl_xor_sync(0xffffffff, p, o);
        if (lane == 0) ((float*)sm)[W_P8 + warpId] = p;
    }

    float* outb = otf + ((size_t)b * NW + bm0) * NW;

#pragma unroll
    for (int mi = 0; mi < 4; mi++) {
        int r0 = wm0 + mi * 16 + lq, r1 = r0 + 8;
        unsigned qk0 = qk_s[r0], qk1 = qk_s[r1];
        float mq0 = qk0 ? 1.0f : 0.0f, mq1 = qk1 ? 1.0f : 0.0f;
        float rs0 = 0.0f, rs1 = 0.0f;
#pragma unroll
        for (int ni = 0; ni < 8; ni++) {
            int c = wn0 + ni * 8 + q * 2;
            unsigned dk0 = dk_s[c], dk1 = dk_s[c + 1];
            float md0 = dk0 ? 1.0f : 0.0f, md1 = dk1 ? 1.0f : 0.0f;
            float tf0 = dtf_s[c], tf1 = dtf_s[c + 1];
            float v00 = acc[mi][ni][0] * (mq0 * md0);
            float v01 = acc[mi][ni][1] * (mq0 * md1);
            float v10 = acc[mi][ni][2] * (mq1 * md0);
            float v11 = acc[mi][ni][3] * (mq1 * md1);
            *(float2*)(outb + (size_t)r0 * NW + c) = make_float2(v00, v01);
            *(float2*)(outb + (size_t)r1 * NW + c) = make_float2(v10, v11);
            rs0 += (v00 * ABf + (qk0 == dk0 ? EMWf : 0.0f)) * tf0
                 + (v01 * ABf + (qk0 == dk1 ? EMWf : 0.0f)) * tf1;
            rs1 += (v10 * ABf + (qk1 == dk0 ? EMWf : 0.0f)) * tf0
                 + (v11 * ABf + (qk1 == dk1 ? EMWf : 0.0f)) * tf1;
        }
        rs0 += __shfl_xor_sync(0xffffffff, rs0, 1);
        rs0 += __shfl_xor_sync(0xffffffff, rs0, 2);
        rs1 += __shfl_xor_sync(0xffffffff, rs1, 1);
        rs1 += __shfl_xor_sync(0xffffffff, rs1, 2);
        if (q == 0) {
            red_s[(warpId & 3) * BM + r0] = rs0;
            red_s[(warpId & 3) * BM + r1] = rs1;
        }
    }
    __syncthreads();

    // ---- fused BM25 finish: per-CTA partial score, one atomicAdd ----
    float val = 0.0f;
    if (tid < BM) {
        const float* p8 = (const float*)sm + W_P8;
        float dl = ((p8[0] + p8[1]) + (p8[2] + p8[3])) + ((p8[4] + p8[5]) + (p8[6] + p8[7]));
        float etdf = (red_s[tid] + red_s[BM + tid]) + (red_s[2 * BM + tid] + red_s[3 * BM + tid]);
        float denom = etdf * (1.0f + K1f);
        float nom   = etdf + K1f * (1.0f - Bpf + Bpf * dl / AVDLf);
        val = qtw[b * NW + bm0 + tid] * (denom / (nom + 1e-8f));
    }
#pragma unroll
    for (int o = 16; o > 0; o >>= 1) val += __shfl_xor_sync(0xffffffff, val, o);
    if (lane == 0 && warpId < 4) ((float*)sm)[W_R2 + warpId] = val;
    __syncthreads();
    if (tid == 0) {
        const float* r2 = (const float*)sm + W_R2;
        // 2 CTAs per batch: float add of two values is commutative -> deterministic
        atomicAdd(score + b, (r2[0] + r2[1]) + (r2[2] + r2[3]));
    }
}

// ============================================================
extern "C" void kernel_launch(void* const* d_in, const int* in_sizes, int n_in,
                              void* d_out, int out_size) {
    const float* q_rep = (const float*)d_in[0];
    const float* d_rep = (const float*)d_in[1];
    const float* qtw   = (const float*)d_in[2];
    const int*   qids  = (const int*)d_in[3];
    const int*   dids  = (const int*)d_in[4];
    const int*   dtfs  = (const int*)d_in[5];

    float* out = (float*)d_out;
    float* otf = out + BATCH;  // d_expanded_tf region

    cudaMemsetAsync(out, 0, BATCH * sizeof(float));
    cudaFuncSetAttribute(gemm_kernel, cudaFuncAttributeMaxDynamicSharedMemorySize, SMEM_BYTES);

    dim3 grid(NW / BM, BATCH);  // (2, 64)
    gemm_kernel<<<grid, NTHREADS, SMEM_BYTES>>>(q_rep, d_rep, qtw, qids, dids, dtfs, otf, out);
}